// round 9
// baseline (speedup 1.0000x reference)
#include <cuda_runtime.h>
#include <cuda_fp16.h>
#include <math.h>
#include <stdint.h>

#define NN 16384
#define EE 65536
#define GG 128
#define DD 64
#define FIN 64
#define EIN 16
#define HE 64
#define LL 3
#define NSTEPS 3
#define EPSV 1e-5f
#define NCHUNK 65              // 64 hidden k + 1 bias chunk
#define BSTRIDE 80             // halfs per o-row (LDS.64 conflict-free)
#define BCH16 (64 * BSTRIDE)   // halfs per chunk image: 5120 (10240 B)

// ---------------- scratch (device globals; no allocation) ----------------
__device__ float d_x[NN * DD];
__device__ float d_agg[NN * DD];
__device__ float d_hT[LL * HE * EE];  // all layers' edge hidden, transposed (48 MB)
__device__ int   d_cnt[NN];
__device__ float d_invc[NN];
__device__ __align__(16) __half d_Bh[LL * NCHUNK * BCH16];  // fp16 B images

// ---------------- helpers ----------------
__device__ __forceinline__ uint32_t packh2(float a, float b) {  // lo=a, hi=b
    uint32_t r;
    asm("cvt.rn.f16x2.f32 %0, %1, %2;" : "=r"(r) : "f"(b), "f"(a));
    return r;
}
__device__ __forceinline__ void hmma(float* c, uint32_t a0, uint32_t a1, uint32_t a2,
                                     uint32_t a3, uint32_t b0, uint32_t b1) {
    asm volatile(
        "mma.sync.aligned.m16n8k16.row.col.f32.f16.f16.f32 "
        "{%0,%1,%2,%3}, {%4,%5,%6,%7}, {%8,%9}, {%0,%1,%2,%3};"
        : "+f"(c[0]), "+f"(c[1]), "+f"(c[2]), "+f"(c[3])
        : "r"(a0), "r"(a1), "r"(a2), "r"(a3), "r"(b0), "r"(b1));
}

// ---------------- [0] zero cnt + agg ----------------
__global__ void k_zero0() {
    int i = blockIdx.x * blockDim.x + threadIdx.x;
    if (i < NN) d_cnt[i] = 0;
    if (i < NN * DD) d_agg[i] = 0.0f;
}
// ---------------- [1] degree count ----------------
__global__ void k_count(const int* __restrict__ dst) {
    int i = blockIdx.x * blockDim.x + threadIdx.x;
    if (i < EE) atomicAdd(&d_cnt[dst[i]], 1);
}
// ---------------- [2] 1/deg ----------------
__global__ void k_invc() {
    int i = blockIdx.x * blockDim.x + threadIdx.x;
    if (i < NN) d_invc[i] = 1.0f / (float)max(d_cnt[i], 1);
}

// ---------------- [3] lin0: x = relu(x_in @ W + b) ----------------
__global__ __launch_bounds__(256) void k_lin0(const float* __restrict__ xin,
                                              const float* __restrict__ w,
                                              const float* __restrict__ b) {
    __shared__ float ws[FIN * DD];
    __shared__ float xs[4][FIN];
    int t = threadIdx.x;
    for (int i = t; i < FIN * DD; i += 256) ws[i] = w[i];
    int n0 = blockIdx.x * 4;
    {
        int li = t >> 6, d = t & 63;
        xs[li][d] = xin[(size_t)(n0 + li) * FIN + d];
    }
    __syncthreads();
    int li = t >> 6, o = t & 63;
    float acc = b[o];
#pragma unroll
    for (int d = 0; d < FIN; d++) acc += xs[li][d] * ws[d * DD + o];
    d_x[(size_t)(n0 + li) * DD + o] = fmaxf(acc, 0.0f);
}

// ---------------- [4] fused prep: all-layer edge hidden + B images ----------------
// blocks [0, 3*512): edge_h for layer bid/512
// blocks [3*512, 3*512 + 3*65): B chunk image prep
__global__ __launch_bounds__(256) void k_prep_all(const float* __restrict__ ea,
                                                  const float* __restrict__ mw1,
                                                  const float* __restrict__ mb1,
                                                  const float* __restrict__ mw2,
                                                  const float* __restrict__ mb2) {
    int bid = blockIdx.x;
    int t = threadIdx.x;
    if (bid < LL * 512) {
        int layer = bid / 512;
        int eb = bid % 512;
        __shared__ float ws[EIN * HE];
        __shared__ float bs[HE];
        const float* w1 = mw1 + (size_t)layer * EIN * HE;
        const float* b1 = mb1 + (size_t)layer * HE;
        for (int i = t; i < EIN * HE; i += 256) ws[i] = w1[i];
        if (t < HE) bs[t] = b1[t];
        __syncthreads();
        int e = eb * 128 + (t & 127);
        int k0 = (t >> 7) * 32;
        float ev[EIN];
        const float4* ep = (const float4*)(ea + (size_t)e * EIN);
#pragma unroll
        for (int i = 0; i < 4; i++) {
            float4 v = ep[i];
            ev[4 * i + 0] = v.x; ev[4 * i + 1] = v.y;
            ev[4 * i + 2] = v.z; ev[4 * i + 3] = v.w;
        }
        float acc[32];
#pragma unroll
        for (int kk = 0; kk < 32; kk++) acc[kk] = bs[k0 + kk];
#pragma unroll
        for (int j = 0; j < EIN; j++) {
            float evj = ev[j];
#pragma unroll
            for (int kk = 0; kk < 32; kk++) acc[kk] += evj * ws[j * HE + k0 + kk];
        }
#pragma unroll
        for (int kk = 0; kk < 32; kk++)
            d_hT[((size_t)layer * HE + k0 + kk) * EE + e] = fmaxf(acc[kk], 0.0f);
    } else {
        int chunk = bid - LL * 512;  // 0 .. LL*NCHUNK-1
        int l = chunk / NCHUNK, kc = chunk % NCHUNK;
        const float* sp = (kc < 64) ? (mw2 + ((size_t)l * 64 + kc) * (DD * DD))
                                    : (mb2 + (size_t)l * (DD * DD));
        __half* hb = d_Bh + (size_t)chunk * BCH16;
        for (int i = t; i < DD * DD; i += 256) {
            int d = i >> 6, o = i & 63;  // sp[i] = M[kc][d][o]
            // interleaved fragment layout: (b0,b1) pair contiguous per (w, tig)
            int w = d >> 4, r = d & 15;
            int hi8 = r >> 3, tig = (r & 7) >> 1, par = r & 1;
            hb[o * BSTRIDE + w * 16 + tig * 4 + par + 2 * hi8] = __float2half_rn(sp[i]);
        }
    }
}

// ---------------- [5,8,11] edge message GEMM, single-pass fp16 HMMA --------------
// Block: 128 edges, 4 warps. Warp tile: 32 edges x 64 outputs.
// msg[e,o] = sum_{kc} h[e,kc] * (y[e,:] @ M[kc][:,o]),  kc==64 is bias (h=1).
__global__ __launch_bounds__(128) void k_edge_msg(const int* __restrict__ src,
                                                  const int* __restrict__ dst,
                                                  int layer) {
    __shared__ __half Bs[BCH16];  // 10240 B
    __shared__ float hs[128];

    int t = threadIdx.x, wid = t >> 5, lid = t & 31;
    int g = lid >> 2, tig = lid & 3;
    int e0 = blockIdx.x * 128;

    // ---- y fragments in registers (constant across chunks) ----
    float yv[4][16];
    int edge_id[4];
#pragma unroll
    for (int mt = 0; mt < 2; mt++)
#pragma unroll
        for (int rr = 0; rr < 2; rr++) {
            int e = e0 + wid * 32 + mt * 16 + g + rr * 8;
            edge_id[mt * 2 + rr] = e;
            const float* xr = d_x + (size_t)src[e] * DD;
#pragma unroll
            for (int w = 0; w < 4; w++) {
                float2 v0 = *(const float2*)(xr + w * 16 + tig * 2);
                float2 v1 = *(const float2*)(xr + w * 16 + 8 + tig * 2);
                yv[mt * 2 + rr][w * 4 + 0] = v0.x;
                yv[mt * 2 + rr][w * 4 + 1] = v0.y;
                yv[mt * 2 + rr][w * 4 + 2] = v1.x;
                yv[mt * 2 + rr][w * 4 + 3] = v1.y;
            }
        }

    float acc[2][8][4];
#pragma unroll
    for (int mt = 0; mt < 2; mt++)
#pragma unroll
        for (int nt = 0; nt < 8; nt++)
#pragma unroll
            for (int q = 0; q < 4; q++) acc[mt][nt][q] = 0.0f;

    const __half* Bh = d_Bh + (size_t)layer * NCHUNK * BCH16;
    const float* hT = d_hT + (size_t)layer * HE * EE;

    // register double-buffer: B chunk = 640 uint4 (5/thread), + h
    uint4 rb[5];
    float rhh;
    {
        const uint4* gB = (const uint4*)Bh;
#pragma unroll
        for (int q = 0; q < 5; q++) rb[q] = gB[t + q * 128];
        rhh = hT[e0 + t];
    }
    {
        uint4* sB = (uint4*)Bs;
#pragma unroll
        for (int q = 0; q < 5; q++) sB[t + q * 128] = rb[q];
        hs[t] = rhh;
    }

    for (int kc = 0; kc < NCHUNK; kc++) {
        __syncthreads();  // Bs/hs for chunk kc visible
        if (kc + 1 < NCHUNK) {  // prefetch next chunk
            const uint4* gB = (const uint4*)(Bh + (size_t)(kc + 1) * BCH16);
#pragma unroll
            for (int q = 0; q < 5; q++) rb[q] = gB[t + q * 128];
            rhh = (kc + 1 < 64) ? hT[(size_t)(kc + 1) * EE + e0 + t] : 1.0f;
        }

        float h0  = hs[wid * 32 + g];
        float h0b = hs[wid * 32 + g + 8];
        float h1  = hs[wid * 32 + 16 + g];
        float h1b = hs[wid * 32 + 16 + g + 8];

#pragma unroll
        for (int w = 0; w < 4; w++) {
            uint32_t ah[2][4];
#pragma unroll
            for (int mt = 0; mt < 2; mt++) {
                float ha = mt ? h1 : h0;
                float hb = mt ? h1b : h0b;
                const float* y0 = yv[mt * 2 + 0];  // row g
                const float* y1 = yv[mt * 2 + 1];  // row g+8
                ah[mt][0] = packh2(ha * y0[w * 4 + 0], ha * y0[w * 4 + 1]);
                ah[mt][1] = packh2(hb * y1[w * 4 + 0], hb * y1[w * 4 + 1]);
                ah[mt][2] = packh2(ha * y0[w * 4 + 2], ha * y0[w * 4 + 3]);
                ah[mt][3] = packh2(hb * y1[w * 4 + 2], hb * y1[w * 4 + 3]);
            }
#pragma unroll
            for (int nt = 0; nt < 8; nt++) {
                uint2 bb = *(const uint2*)(Bs + (nt * 8 + g) * BSTRIDE + w * 16 + tig * 4);
#pragma unroll
                for (int mt = 0; mt < 2; mt++)
                    hmma(acc[mt][nt], ah[mt][0], ah[mt][1], ah[mt][2], ah[mt][3],
                         bb.x, bb.y);
            }
        }
        __syncthreads();  // all reads of Bs/hs done
        if (kc + 1 < NCHUNK) {
            uint4* sB = (uint4*)Bs;
#pragma unroll
            for (int q = 0; q < 5; q++) sB[t + q * 128] = rb[q];
            hs[t] = rhh;
        }
    }

    // ---- scatter: agg[dst] += msg / deg ----
#pragma unroll
    for (int mt = 0; mt < 2; mt++)
#pragma unroll
        for (int rr = 0; rr < 2; rr++) {
            int e = edge_id[mt * 2 + rr];
            int dn = dst[e];
            float ic = d_invc[dn];
            float* p = d_agg + (size_t)dn * DD + tig * 2;
#pragma unroll
            for (int nt = 0; nt < 8; nt++) {
                atomicAdd(&p[nt * 8 + 0], acc[mt][nt][rr * 2 + 0] * ic);
                atomicAdd(&p[nt * 8 + 1], acc[mt][nt][rr * 2 + 1] * ic);
            }
        }
}

// ---------------- root: xc = relu(agg + x @ root_w + b) ----------------
__global__ __launch_bounds__(256) void k_root(const float* __restrict__ w,
                                              const float* __restrict__ b) {
    __shared__ float ws[DD * DD];
    __shared__ float xs[4][DD];
    int t = threadIdx.x;
    for (int i = t; i < DD * DD; i += 256) ws[i] = w[i];
    int n0 = blockIdx.x * 4;
    {
        int li = t >> 6, d = t & 63;
        xs[li][d] = d_x[(size_t)(n0 + li) * DD + d];
    }
    __syncthreads();
    int li = t >> 6, o = t & 63;
    size_t idx = (size_t)(n0 + li) * DD + o;
    float acc = b[o] + d_agg[idx];
#pragma unroll
    for (int d = 0; d < DD; d++) acc += xs[li][d] * ws[d * DD + o];
    d_agg[idx] = fmaxf(acc, 0.0f);
}

// ---------------- GraphNorm + residual; also zeroes agg for next layer ----------
__global__ __launch_bounds__(256) void k_gnorm(const float* __restrict__ gw,
                                               const float* __restrict__ gb,
                                               const float* __restrict__ gs) {
    __shared__ float s[128][DD + 1];
    __shared__ float mean[DD];
    __shared__ float var[DD];
    int g = blockIdx.x, t = threadIdx.x;
    const float* xc = d_agg + (size_t)g * 128 * DD;
    for (int i = t; i < 128 * DD; i += 256) s[i >> 6][i & 63] = xc[i];
    __syncthreads();
    if (t < DD) {
        float m = 0.0f;
        for (int n = 0; n < 128; n++) m += s[n][t];
        mean[t] = m * (1.0f / 128.0f);
    }
    __syncthreads();
    for (int i = t; i < 128 * DD; i += 256) {
        int n = i >> 6, d = i & 63;
        s[n][d] -= gs[d] * mean[d];
    }
    __syncthreads();
    if (t < DD) {
        float v = 0.0f;
        for (int n = 0; n < 128; n++) v += s[n][t] * s[n][t];
        var[t] = v * (1.0f / 128.0f);
    }
    __syncthreads();
    for (int i = t; i < 128 * DD; i += 256) {
        int n = i >> 6, d = i & 63;
        float xn = gw[d] * s[n][d] * rsqrtf(var[d] + EPSV) + gb[d];
        size_t gi = (size_t)g * 128 * DD + i;
        d_x[gi] = xn + d_x[gi];
        d_agg[gi] = 0.0f;  // ready for next layer's scatter
    }
}

// ---------------- Set2Set (3 steps) + head, one block per graph ----------------
__global__ __launch_bounds__(128) void k_s2s(const float* __restrict__ wih,
                                             const float* __restrict__ whh,
                                             const float* __restrict__ bih,
                                             const float* __restrict__ bhh,
                                             const float* __restrict__ hw1,
                                             const float* __restrict__ hb1,
                                             const float* __restrict__ hw2,
                                             const float* __restrict__ hb2,
                                             float* __restrict__ out) {
    __shared__ float sx[128][DD + 1];
    __shared__ float q_star[2 * DD];
    __shared__ float sh[DD], sc[DD];
    __shared__ float gates[4 * DD];
    __shared__ float red[128];
    __shared__ float sa[128];
    __shared__ float sr[DD];
    int g = blockIdx.x, t = threadIdx.x;
    const float* xg = d_x + (size_t)g * 128 * DD;
    for (int i = t; i < 128 * DD; i += 128) sx[i >> 6][i & 63] = xg[i];
    q_star[t] = 0.0f;
    if (t < DD) { sh[t] = 0.0f; sc[t] = 0.0f; }
    __syncthreads();

    for (int step = 0; step < NSTEPS; step++) {
#pragma unroll
        for (int rr = 0; rr < 2; rr++) {
            int r = t + rr * 128;
            float acc = bih[r] + bhh[r];
            const float* wr = wih + (size_t)r * (2 * DD);
            for (int j = 0; j < 2 * DD; j++) acc += q_star[j] * wr[j];
            const float* vr = whh + (size_t)r * DD;
            for (int j = 0; j < DD; j++) acc += sh[j] * vr[j];
            gates[r] = acc;
        }
        __syncthreads();
        if (t < DD) {
            float ig = 1.0f / (1.0f + expf(-gates[t]));
            float fg = 1.0f / (1.0f + expf(-gates[DD + t]));
            float gg = tanhf(gates[2 * DD + t]);
            float og = 1.0f / (1.0f + expf(-gates[3 * DD + t]));
            float c = fg * sc[t] + ig * gg;
            sc[t] = c;
            sh[t] = og * tanhf(c);
        }
        __syncthreads();
        float ee = 0.0f;
#pragma unroll
        for (int d = 0; d < DD; d++) ee += sx[t][d] * sh[d];
        red[t] = ee;
        __syncthreads();
        for (int off = 64; off; off >>= 1) {
            if (t < off) red[t] = fmaxf(red[t], red[t + off]);
            __syncthreads();
        }
        float emax = red[0];
        __syncthreads();
        float ex = expf(ee - emax);
        red[t] = ex;
        __syncthreads();
        for (int off = 64; off; off >>= 1) {
            if (t < off) red[t] += red[t + off];
            __syncthreads();
        }
        float denom = red[0];
        sa[t] = ex / denom;
        __syncthreads();
        if (t < DD) {
            float r = 0.0f;
            for (int n = 0; n < 128; n++) r += sa[n] * sx[n][t];
            sr[t] = r;
        }
        __syncthreads();
        q_star[t] = (t < DD) ? sh[t] : sr[t - DD];
        __syncthreads();
    }
    if (t < DD) {
        float acc = hb1[t];
        for (int j = 0; j < 2 * DD; j++) acc += q_star[j] * hw1[j * DD + t];
        red[t] = fmaxf(acc, 0.0f) * hw2[t];
    }
    __syncthreads();
    if (t < 32) {
        float v = red[t] + red[t + 32];
        for (int off = 16; off; off >>= 1) v += __shfl_down_sync(0xffffffffu, v, off);
        if (t == 0) out[g] = v + hb2[0];
    }
}

// ---------------- launch ----------------
extern "C" void kernel_launch(void* const* d_in, const int* in_sizes, int n_in,
                              void* d_out, int out_size) {
    const float* x     = (const float*)d_in[0];
    const int*   ei    = (const int*)d_in[1];
    const float* ea    = (const float*)d_in[2];
    const float* lin0w = (const float*)d_in[4];
    const float* lin0b = (const float*)d_in[5];
    const float* mw1   = (const float*)d_in[6];
    const float* mb1   = (const float*)d_in[7];
    const float* mw2   = (const float*)d_in[8];
    const float* mb2   = (const float*)d_in[9];
    const float* rootw = (const float*)d_in[10];
    const float* convb = (const float*)d_in[11];
    const float* gnw   = (const float*)d_in[12];
    const float* gnb   = (const float*)d_in[13];
    const float* gns   = (const float*)d_in[14];
    const float* wih   = (const float*)d_in[15];
    const float* whh   = (const float*)d_in[16];
    const float* bih   = (const float*)d_in[17];
    const float* bhh   = (const float*)d_in[18];
    const float* hw1   = (const float*)d_in[19];
    const float* hb1   = (const float*)d_in[20];
    const float* hw2   = (const float*)d_in[21];
    const float* hb2   = (const float*)d_in[22];
    float* out = (float*)d_out;

    const int* src = ei;
    const int* dst = ei + EE;

    k_zero0<<<(NN * DD) / 256, 256>>>();                              // [0]
    k_count<<<EE / 256, 256>>>(dst);                                  // [1]
    k_invc<<<NN / 256, 256>>>();                                      // [2]
    k_lin0<<<NN / 4, 256>>>(x, lin0w, lin0b);                         // [3]
    k_prep_all<<<LL * 512 + LL * NCHUNK, 256>>>(ea, mw1, mb1, mw2, mb2);  // [4]

    for (int l = 0; l < LL; l++) {
        k_edge_msg<<<EE / 128, 128>>>(src, dst, l);                   // [5], [8], [11]
        k_root<<<NN / 4, 256>>>(rootw + (size_t)l * DD * DD, convb + (size_t)l * DD);
        k_gnorm<<<GG, 256>>>(gnw + (size_t)l * DD, gnb + (size_t)l * DD, gns + (size_t)l * DD);
    }

    k_s2s<<<GG, 128>>>(wih, whh, bih, bhh, hw1, hb1, hw2, hb2, out);  // [14]
}

// round 10
// speedup vs baseline: 1.0657x; 1.0657x over previous
#include <cuda_runtime.h>
#include <cuda_fp16.h>
#include <math.h>
#include <stdint.h>

#define NN 16384
#define EE 65536
#define GG 128
#define DD 64
#define FIN 64
#define EIN 16
#define HE 64
#define LL 3
#define NSTEPS 3
#define EPSV 1e-5f
#define NCHUNK 65              // 64 hidden k + 1 bias chunk
#define BSTRIDE 72             // padded fp16 row stride (conflict-free LDS)
#define BCH16 (64 * BSTRIDE)   // halfs per chunk image: 4608 (9216 B)

// ---------------- scratch (device globals; no allocation) ----------------
__device__ float d_x[NN * DD];
__device__ float d_agg[NN * DD];
__device__ float d_hT[NCHUNK * EE];  // edge hidden transposed + ones row (17 MB)
__device__ int   d_cnt[NN];
__device__ float d_invc[NN];
__device__ __align__(16) __half d_Bh[LL * NCHUNK * BCH16];  // fp16 B images

// ---------------- helpers ----------------
__device__ __forceinline__ uint32_t smem_u32(const void* p) {
    return (uint32_t)__cvta_generic_to_shared(p);
}
__device__ __forceinline__ uint32_t packh2(float a, float b) {  // lo=a, hi=b
    uint32_t r;
    asm("cvt.rn.f16x2.f32 %0, %1, %2;" : "=r"(r) : "f"(b), "f"(a));
    return r;
}
__device__ __forceinline__ float2 h2f2(uint32_t p) {  // unpack fp16x2 -> floats
    float2 f;
    asm("{.reg .b16 l, h;\n\t mov.b32 {l, h}, %2;\n\t"
        "cvt.f32.f16 %0, l;\n\t cvt.f32.f16 %1, h;}"
        : "=f"(f.x), "=f"(f.y) : "r"(p));
    return f;
}
__device__ __forceinline__ void hmma(float* c, uint32_t a0, uint32_t a1, uint32_t a2,
                                     uint32_t a3, uint32_t b0, uint32_t b1) {
    asm volatile(
        "mma.sync.aligned.m16n8k16.row.col.f32.f16.f16.f32 "
        "{%0,%1,%2,%3}, {%4,%5,%6,%7}, {%8,%9}, {%0,%1,%2,%3};"
        : "+f"(c[0]), "+f"(c[1]), "+f"(c[2]), "+f"(c[3])
        : "r"(a0), "r"(a1), "r"(a2), "r"(a3), "r"(b0), "r"(b1));
}
#define CP_A16(s, g) asm volatile("cp.async.ca.shared.global [%0], [%1], 16;" :: "r"(s), "l"(g))
#define CP_A4(s, g)  asm volatile("cp.async.ca.shared.global [%0], [%1], 4;"  :: "r"(s), "l"(g))
#define CP_COMMIT()  asm volatile("cp.async.commit_group;")
#define CP_WAIT1()   asm volatile("cp.async.wait_group 1;")
#define CP_WAIT0()   asm volatile("cp.async.wait_group 0;")

// ---------------- small utility kernels ----------------
__global__ void k_zero_cnt() {
    int i = blockIdx.x * blockDim.x + threadIdx.x;
    if (i < NN) d_cnt[i] = 0;
}
__global__ void k_count(const int* __restrict__ dst) {
    int i = blockIdx.x * blockDim.x + threadIdx.x;
    if (i < EE) atomicAdd(&d_cnt[dst[i]], 1);
}
__global__ void k_invc() {
    int i = blockIdx.x * blockDim.x + threadIdx.x;
    if (i < NN) d_invc[i] = 1.0f / (float)max(d_cnt[i], 1);
}
__global__ void k_zero_agg() {
    int i = blockIdx.x * blockDim.x + threadIdx.x;
    if (i < NN * DD) d_agg[i] = 0.0f;
}
__global__ void k_ones() {  // hT row 64 = 1.0 (bias chunk); written once, never clobbered
    int i = blockIdx.x * blockDim.x + threadIdx.x;
    if (i < EE) d_hT[(size_t)64 * EE + i] = 1.0f;
}

// ---------------- prep: B chunk images (o-major rows, padded stride, fp16) --------
__global__ void k_prep_B(const float* __restrict__ mw2, const float* __restrict__ mb2) {
    int chunk = blockIdx.x;  // 0 .. LL*NCHUNK-1
    int l = chunk / NCHUNK, kc = chunk % NCHUNK;
    const float* sp = (kc < 64) ? (mw2 + ((size_t)l * 64 + kc) * (DD * DD))
                                : (mb2 + (size_t)l * (DD * DD));
    __half* hb = d_Bh + (size_t)chunk * BCH16;
    for (int i = threadIdx.x; i < DD * DD; i += 256) {
        int d = i >> 6, o = i & 63;  // sp[i] = M[kc][d][o]
        hb[o * BSTRIDE + d] = __float2half_rn(sp[i]);
    }
}

// ---------------- lin0: x = relu(x_in @ W + b) ----------------
__global__ __launch_bounds__(256) void k_lin0(const float* __restrict__ xin,
                                              const float* __restrict__ w,
                                              const float* __restrict__ b) {
    __shared__ float ws[FIN * DD];
    __shared__ float xs[4][FIN];
    int t = threadIdx.x;
    for (int i = t; i < FIN * DD; i += 256) ws[i] = w[i];
    int n0 = blockIdx.x * 4;
    {
        int li = t >> 6, d = t & 63;
        xs[li][d] = xin[(size_t)(n0 + li) * FIN + d];
    }
    __syncthreads();
    int li = t >> 6, o = t & 63;
    float acc = b[o];
#pragma unroll
    for (int d = 0; d < FIN; d++) acc += xs[li][d] * ws[d * DD + o];
    d_x[(size_t)(n0 + li) * DD + o] = fmaxf(acc, 0.0f);
}

// ---------------- edge hidden, transposed: hT[k][e] = relu(ea @ W1 + b1) ----------
__global__ __launch_bounds__(256) void k_edge_h(const float* __restrict__ ea,
                                                const float* __restrict__ w1,
                                                const float* __restrict__ b1) {
    __shared__ float ws[EIN * HE];
    __shared__ float bs[HE];
    int t = threadIdx.x;
    for (int i = t; i < EIN * HE; i += 256) ws[i] = w1[i];
    if (t < HE) bs[t] = b1[t];
    __syncthreads();
    int e = blockIdx.x * 128 + (t & 127);
    int k0 = (t >> 7) * 32;
    float ev[EIN];
    const float4* ep = (const float4*)(ea + (size_t)e * EIN);
#pragma unroll
    for (int i = 0; i < 4; i++) {
        float4 v = ep[i];
        ev[4 * i + 0] = v.x; ev[4 * i + 1] = v.y;
        ev[4 * i + 2] = v.z; ev[4 * i + 3] = v.w;
    }
    float acc[32];
#pragma unroll
    for (int kk = 0; kk < 32; kk++) acc[kk] = bs[k0 + kk];
#pragma unroll
    for (int j = 0; j < EIN; j++) {
        float evj = ev[j];
#pragma unroll
        for (int kk = 0; kk < 32; kk++) acc[kk] += evj * ws[j * HE + k0 + kk];
    }
#pragma unroll
    for (int kk = 0; kk < 32; kk++)
        d_hT[(size_t)(k0 + kk) * EE + e] = fmaxf(acc[kk], 0.0f);
}

// ---------------- edge message GEMM via warp MMA (fp16 split-A, 2 passes) ---------
// Block: 128 edges, 4 warps. Warp tile: 32 edges x 64 outputs.
// B/h staged via cp.async double-buffer (no register round-trip).
__global__ __launch_bounds__(128) void k_edge_msg_hmma(const int* __restrict__ src,
                                                       const int* __restrict__ dst,
                                                       int layer) {
    __shared__ __half Bs[2][BCH16];  // 2 x 9216 B
    __shared__ float hs[2][128];

    int t = threadIdx.x, wid = t >> 5, lid = t & 31;
    int g = lid >> 2, tig = lid & 3;
    int e0 = blockIdx.x * 128;

    // ---- y fragments in registers (constant across chunks) ----
    float yv[4][16];
    int edge_id[4];
#pragma unroll
    for (int mt = 0; mt < 2; mt++)
#pragma unroll
        for (int rr = 0; rr < 2; rr++) {
            int e = e0 + wid * 32 + mt * 16 + g + rr * 8;
            edge_id[mt * 2 + rr] = e;
            const float* xr = d_x + (size_t)src[e] * DD;
#pragma unroll
            for (int w = 0; w < 4; w++) {
                float2 v0 = *(const float2*)(xr + w * 16 + tig * 2);
                float2 v1 = *(const float2*)(xr + w * 16 + 8 + tig * 2);
                yv[mt * 2 + rr][w * 4 + 0] = v0.x;
                yv[mt * 2 + rr][w * 4 + 1] = v0.y;
                yv[mt * 2 + rr][w * 4 + 2] = v1.x;
                yv[mt * 2 + rr][w * 4 + 3] = v1.y;
            }
        }

    float acc[2][8][4];
#pragma unroll
    for (int mt = 0; mt < 2; mt++)
#pragma unroll
        for (int nt = 0; nt < 8; nt++)
#pragma unroll
            for (int q = 0; q < 4; q++) acc[mt][nt][q] = 0.0f;

    const __half* Bh = d_Bh + (size_t)layer * NCHUNK * BCH16;

    uint32_t sB0 = smem_u32(&Bs[0][0]);
    uint32_t sB1 = smem_u32(&Bs[1][0]);
    uint32_t sh0 = smem_u32(&hs[0][0]);
    uint32_t sh1 = smem_u32(&hs[1][0]);

    // async copy of one chunk (B: 576x16B across 128 threads; h: 4B/thread)
    auto issue_chunk = [&](int kc, int st) {
        const char* gB = (const char*)(Bh + (size_t)kc * BCH16);
        uint32_t sB = st ? sB1 : sB0;
        uint32_t sh = st ? sh1 : sh0;
#pragma unroll
        for (int q = 0; q < 4; q++)
            CP_A16(sB + (t + q * 128) * 16, gB + (size_t)(t + q * 128) * 16);
        if (t < 64) CP_A16(sB + (t + 512) * 16, gB + (size_t)(t + 512) * 16);
        CP_A4(sh + t * 4, (const char*)(d_hT + (size_t)kc * EE + e0 + t));
    };

    issue_chunk(0, 0);
    CP_COMMIT();

    for (int kc = 0; kc < NCHUNK; kc++) {
        int st = kc & 1;
        __syncthreads();  // all warps finished compute(kc-1) -> safe to refill buf st^1
        if (kc + 1 < NCHUNK) {
            issue_chunk(kc + 1, st ^ 1);
            CP_COMMIT();
            CP_WAIT1();   // chunk kc's copies (this thread's) complete
        } else {
            CP_WAIT0();
        }
        __syncthreads();  // whole buffer st published

        float h0  = hs[st][wid * 32 + g];
        float h0b = hs[st][wid * 32 + g + 8];
        float h1  = hs[st][wid * 32 + 16 + g];
        float h1b = hs[st][wid * 32 + 16 + g + 8];

#pragma unroll
        for (int w = 0; w < 4; w++) {
            uint32_t ahi[2][4], alo[2][4];
#pragma unroll
            for (int mt = 0; mt < 2; mt++) {
                float ha = mt ? h1 : h0;
                float hb = mt ? h1b : h0b;
                const float* y0 = yv[mt * 2 + 0];  // row g
                const float* y1 = yv[mt * 2 + 1];  // row g+8
                float p00 = ha * y0[w * 4 + 0], p01 = ha * y0[w * 4 + 1];
                float p02 = ha * y0[w * 4 + 2], p03 = ha * y0[w * 4 + 3];
                float p10 = hb * y1[w * 4 + 0], p11 = hb * y1[w * 4 + 1];
                float p12 = hb * y1[w * 4 + 2], p13 = hb * y1[w * 4 + 3];
                uint32_t A0 = packh2(p00, p01), A1 = packh2(p10, p11);
                uint32_t A2 = packh2(p02, p03), A3 = packh2(p12, p13);
                ahi[mt][0] = A0; ahi[mt][1] = A1; ahi[mt][2] = A2; ahi[mt][3] = A3;
                float2 q0 = h2f2(A0), q1 = h2f2(A1), q2 = h2f2(A2), q3 = h2f2(A3);
                alo[mt][0] = packh2(p00 - q0.x, p01 - q0.y);
                alo[mt][1] = packh2(p10 - q1.x, p11 - q1.y);
                alo[mt][2] = packh2(p02 - q2.x, p03 - q2.y);
                alo[mt][3] = packh2(p12 - q3.x, p13 - q3.y);
            }
#pragma unroll
            for (int nt = 0; nt < 8; nt++) {
                int boff = (nt * 8 + g) * BSTRIDE + w * 16 + tig * 2;
                uint32_t b0 = *(const uint32_t*)(&Bs[st][0] + boff);
                uint32_t b1 = *(const uint32_t*)(&Bs[st][0] + boff + 8);
#pragma unroll
                for (int mt = 0; mt < 2; mt++) {
                    hmma(acc[mt][nt], ahi[mt][0], ahi[mt][1], ahi[mt][2], ahi[mt][3], b0, b1);
                    hmma(acc[mt][nt], alo[mt][0], alo[mt][1], alo[mt][2], alo[mt][3], b0, b1);
                }
            }
        }
    }

    // ---- scatter: agg[dst] += msg / deg ----
#pragma unroll
    for (int mt = 0; mt < 2; mt++)
#pragma unroll
        for (int rr = 0; rr < 2; rr++) {
            int e = edge_id[mt * 2 + rr];
            int dn = dst[e];
            float ic = d_invc[dn];
            float* p = d_agg + (size_t)dn * DD + tig * 2;
#pragma unroll
            for (int nt = 0; nt < 8; nt++) {
                atomicAdd(&p[nt * 8 + 0], acc[mt][nt][rr * 2 + 0] * ic);
                atomicAdd(&p[nt * 8 + 1], acc[mt][nt][rr * 2 + 1] * ic);
            }
        }
}

// ---------------- root: xc = relu(agg + x @ root_w + b) ----------------
__global__ __launch_bounds__(256) void k_root(const float* __restrict__ w,
                                              const float* __restrict__ b) {
    __shared__ float ws[DD * DD];
    __shared__ float xs[4][DD];
    int t = threadIdx.x;
    for (int i = t; i < DD * DD; i += 256) ws[i] = w[i];
    int n0 = blockIdx.x * 4;
    {
        int li = t >> 6, d = t & 63;
        xs[li][d] = d_x[(size_t)(n0 + li) * DD + d];
    }
    __syncthreads();
    int li = t >> 6, o = t & 63;
    size_t idx = (size_t)(n0 + li) * DD + o;
    float acc = b[o] + d_agg[idx];
#pragma unroll
    for (int d = 0; d < DD; d++) acc += xs[li][d] * ws[d * DD + o];
    d_agg[idx] = fmaxf(acc, 0.0f);
}

// ---------------- GraphNorm + residual (one block per graph) ----------------
__global__ __launch_bounds__(256) void k_gnorm(const float* __restrict__ gw,
                                               const float* __restrict__ gb,
                                               const float* __restrict__ gs) {
    __shared__ float s[128][DD + 1];
    __shared__ float mean[DD];
    __shared__ float var[DD];
    int g = blockIdx.x, t = threadIdx.x;
    const float* xc = d_agg + (size_t)g * 128 * DD;
    for (int i = t; i < 128 * DD; i += 256) s[i >> 6][i & 63] = xc[i];
    __syncthreads();
    if (t < DD) {
        float m = 0.0f;
        for (int n = 0; n < 128; n++) m += s[n][t];
        mean[t] = m * (1.0f / 128.0f);
    }
    __syncthreads();
    for (int i = t; i < 128 * DD; i += 256) {
        int n = i >> 6, d = i & 63;
        s[n][d] -= gs[d] * mean[d];
    }
    __syncthreads();
    if (t < DD) {
        float v = 0.0f;
        for (int n = 0; n < 128; n++) v += s[n][t] * s[n][t];
        var[t] = v * (1.0f / 128.0f);
    }
    __syncthreads();
    for (int i = t; i < 128 * DD; i += 256) {
        int n = i >> 6, d = i & 63;
        float xn = gw[d] * s[n][d] * rsqrtf(var[d] + EPSV) + gb[d];
        size_t gi = (size_t)g * 128 * DD + i;
        d_x[gi] = xn + d_x[gi];
    }
}

// ---------------- Set2Set (3 steps) + head, one block per graph ----------------
__global__ __launch_bounds__(128) void k_s2s(const float* __restrict__ wih,
                                             const float* __restrict__ whh,
                                             const float* __restrict__ bih,
                                             const float* __restrict__ bhh,
                                             const float* __restrict__ hw1,
                                             const float* __restrict__ hb1,
                                             const float* __restrict__ hw2,
                                             const float* __restrict__ hb2,
                                             float* __restrict__ out) {
    __shared__ float sx[128][DD + 1];
    __shared__ float q_star[2 * DD];
    __shared__ float sh[DD], sc[DD];
    __shared__ float gates[4 * DD];
    __shared__ float red[128];
    __shared__ float sa[128];
    __shared__ float sr[DD];
    int g = blockIdx.x, t = threadIdx.x;
    const float* xg = d_x + (size_t)g * 128 * DD;
    for (int i = t; i < 128 * DD; i += 128) sx[i >> 6][i & 63] = xg[i];
    q_star[t] = 0.0f;
    if (t < DD) { sh[t] = 0.0f; sc[t] = 0.0f; }
    __syncthreads();

    for (int step = 0; step < NSTEPS; step++) {
#pragma unroll
        for (int rr = 0; rr < 2; rr++) {
            int r = t + rr * 128;
            float acc = bih[r] + bhh[r];
            const float* wr = wih + (size_t)r * (2 * DD);
            for (int j = 0; j < 2 * DD; j++) acc += q_star[j] * wr[j];
            const float* vr = whh + (size_t)r * DD;
            for (int j = 0; j < DD; j++) acc += sh[j] * vr[j];
            gates[r] = acc;
        }
        __syncthreads();
        if (t < DD) {
            float ig = 1.0f / (1.0f + expf(-gates[t]));
            float fg = 1.0f / (1.0f + expf(-gates[DD + t]));
            float gg = tanhf(gates[2 * DD + t]);
            float og = 1.0f / (1.0f + expf(-gates[3 * DD + t]));
            float c = fg * sc[t] + ig * gg;
            sc[t] = c;
            sh[t] = og * tanhf(c);
        }
        __syncthreads();
        float ee = 0.0f;
#pragma unroll
        for (int d = 0; d < DD; d++) ee += sx[t][d] * sh[d];
        red[t] = ee;
        __syncthreads();
        for (int off = 64; off; off >>= 1) {
            if (t < off) red[t] = fmaxf(red[t], red[t + off]);
            __syncthreads();
        }
        float emax = red[0];
        __syncthreads();
        float ex = expf(ee - emax);
        red[t] = ex;
        __syncthreads();
        for (int off = 64; off; off >>= 1) {
            if (t < off) red[t] += red[t + off];
            __syncthreads();
        }
        float denom = red[0];
        sa[t] = ex / denom;
        __syncthreads();
        if (t < DD) {
            float r = 0.0f;
            for (int n = 0; n < 128; n++) r += sa[n] * sx[n][t];
            sr[t] = r;
        }
        __syncthreads();
        q_star[t] = (t < DD) ? sh[t] : sr[t - DD];
        __syncthreads();
    }
    if (t < DD) {
        float acc = hb1[t];
        for (int j = 0; j < 2 * DD; j++) acc += q_star[j] * hw1[j * DD + t];
        red[t] = fmaxf(acc, 0.0f) * hw2[t];
    }
    __syncthreads();
    if (t < 32) {
        float v = red[t] + red[t + 32];
        for (int off = 16; off; off >>= 1) v += __shfl_down_sync(0xffffffffu, v, off);
        if (t == 0) out[g] = v + hb2[0];
    }
}

// ---------------- launch ----------------
extern "C" void kernel_launch(void* const* d_in, const int* in_sizes, int n_in,
                              void* d_out, int out_size) {
    const float* x     = (const float*)d_in[0];
    const int*   ei    = (const int*)d_in[1];
    const float* ea    = (const float*)d_in[2];
    const float* lin0w = (const float*)d_in[4];
    const float* lin0b = (const float*)d_in[5];
    const float* mw1   = (const float*)d_in[6];
    const float* mb1   = (const float*)d_in[7];
    const float* mw2   = (const float*)d_in[8];
    const float* mb2   = (const float*)d_in[9];
    const float* rootw = (const float*)d_in[10];
    const float* convb = (const float*)d_in[11];
    const float* gnw   = (const float*)d_in[12];
    const float* gnb   = (const float*)d_in[13];
    const float* gns   = (const float*)d_in[14];
    const float* wih   = (const float*)d_in[15];
    const float* whh   = (const float*)d_in[16];
    const float* bih   = (const float*)d_in[17];
    const float* bhh   = (const float*)d_in[18];
    const float* hw1   = (const float*)d_in[19];
    const float* hb1   = (const float*)d_in[20];
    const float* hw2   = (const float*)d_in[21];
    const float* hb2   = (const float*)d_in[22];
    float* out = (float*)d_out;

    const int* src = ei;
    const int* dst = ei + EE;

    k_zero_cnt<<<NN / 256, 256>>>();
    k_count<<<EE / 256, 256>>>(dst);
    k_invc<<<NN / 256, 256>>>();
    k_lin0<<<NN / 4, 256>>>(x, lin0w, lin0b);
    k_prep_B<<<LL * NCHUNK, 256>>>(mw2, mb2);
    k_ones<<<EE / 256, 256>>>();

    for (int l = 0; l < LL; l++) {
        k_zero_agg<<<(NN * DD) / 256, 256>>>();
        k_edge_h<<<EE / 128, 256>>>(ea, mw1 + (size_t)l * EIN * HE, mb1 + (size_t)l * HE);
        k_edge_msg_hmma<<<EE / 128, 128>>>(src, dst, l);
        k_root<<<NN / 4, 256>>>(rootw + (size_t)l * DD * DD, convb + (size_t)l * DD);
        k_gnorm<<<GG, 256>>>(gnw + (size_t)l * DD, gnb + (size_t)l * DD, gns + (size_t)l * DD);
    }

    k_s2s<<<GG, 128>>>(wih, whh, bih, bhh, hw1, hb1, hw2, hb2, out);
}

// round 11
// speedup vs baseline: 1.5984x; 1.4998x over previous
#include <cuda_runtime.h>
#include <cuda_fp16.h>
#include <math.h>
#include <stdint.h>

#define NN 16384
#define EE 65536
#define GG 128
#define DD 64
#define FIN 64
#define EIN 16
#define HE 64
#define LL 3
#define NSTEPS 3
#define EPSV 1e-5f
#define NCHUNK 65              // 64 hidden k + 1 bias chunk
#define BSTRIDE 72             // padded fp16 row stride (conflict-free LDS)
#define BCH16 (64 * BSTRIDE)   // halfs per chunk image: 4608 (9216 B)

// ---------------- scratch (device globals; no allocation) ----------------
__device__ float d_x[NN * DD];
__device__ float d_agg[NN * DD];
__device__ float d_hT[NCHUNK * EE];  // edge hidden transposed + ones row (17 MB)
__device__ int   d_cnt[NN];
__device__ float d_invc[NN];
__device__ __align__(16) __half d_Bh[LL * NCHUNK * BCH16];  // fp16 B images

// ---------------- helpers ----------------
__device__ __forceinline__ uint32_t smem_u32(const void* p) {
    return (uint32_t)__cvta_generic_to_shared(p);
}
__device__ __forceinline__ uint32_t packh2(float a, float b) {  // lo=a, hi=b
    uint32_t r;
    asm("cvt.rn.f16x2.f32 %0, %1, %2;" : "=r"(r) : "f"(b), "f"(a));
    return r;
}
__device__ __forceinline__ void hmma(float* c, uint32_t a0, uint32_t a1, uint32_t a2,
                                     uint32_t a3, uint32_t b0, uint32_t b1) {
    asm volatile(
        "mma.sync.aligned.m16n8k16.row.col.f32.f16.f16.f32 "
        "{%0,%1,%2,%3}, {%4,%5,%6,%7}, {%8,%9}, {%0,%1,%2,%3};"
        : "+f"(c[0]), "+f"(c[1]), "+f"(c[2]), "+f"(c[3])
        : "r"(a0), "r"(a1), "r"(a2), "r"(a3), "r"(b0), "r"(b1));
}
#define CP_A16(s, g) asm volatile("cp.async.ca.shared.global [%0], [%1], 16;" :: "r"(s), "l"(g))
#define CP_A4(s, g)  asm volatile("cp.async.ca.shared.global [%0], [%1], 4;"  :: "r"(s), "l"(g))
#define CP_COMMIT()  asm volatile("cp.async.commit_group;")
#define CP_WAIT1()   asm volatile("cp.async.wait_group 1;")
#define CP_WAIT0()   asm volatile("cp.async.wait_group 0;")

// ---------------- small utility kernels ----------------
__global__ void k_zero_cnt() {
    int i = blockIdx.x * blockDim.x + threadIdx.x;
    if (i < NN) d_cnt[i] = 0;
}
__global__ void k_count(const int* __restrict__ dst) {
    int i = blockIdx.x * blockDim.x + threadIdx.x;
    if (i < EE) atomicAdd(&d_cnt[dst[i]], 1);
}
__global__ void k_invc() {
    int i = blockIdx.x * blockDim.x + threadIdx.x;
    if (i < NN) d_invc[i] = 1.0f / (float)max(d_cnt[i], 1);
}
__global__ void k_zero_agg() {
    int i = blockIdx.x * blockDim.x + threadIdx.x;
    if (i < NN * DD) d_agg[i] = 0.0f;
}
__global__ void k_ones() {  // hT row 64 = 1.0 (bias chunk)
    int i = blockIdx.x * blockDim.x + threadIdx.x;
    if (i < EE) d_hT[(size_t)64 * EE + i] = 1.0f;
}

// ---------------- prep: B chunk images (o-major rows, padded stride, fp16) --------
__global__ void k_prep_B(const float* __restrict__ mw2, const float* __restrict__ mb2) {
    int chunk = blockIdx.x;  // 0 .. LL*NCHUNK-1
    int l = chunk / NCHUNK, kc = chunk % NCHUNK;
    const float* sp = (kc < 64) ? (mw2 + ((size_t)l * 64 + kc) * (DD * DD))
                                : (mb2 + (size_t)l * (DD * DD));
    __half* hb = d_Bh + (size_t)chunk * BCH16;
    for (int i = threadIdx.x; i < DD * DD; i += 256) {
        int d = i >> 6, o = i & 63;  // sp[i] = M[kc][d][o]
        hb[o * BSTRIDE + d] = __float2half_rn(sp[i]);
    }
}

// ---------------- lin0: x = relu(x_in @ W + b) ----------------
__global__ __launch_bounds__(256) void k_lin0(const float* __restrict__ xin,
                                              const float* __restrict__ w,
                                              const float* __restrict__ b) {
    __shared__ float ws[FIN * DD];
    __shared__ float xs[4][FIN];
    int t = threadIdx.x;
    for (int i = t; i < FIN * DD; i += 256) ws[i] = w[i];
    int n0 = blockIdx.x * 4;
    {
        int li = t >> 6, d = t & 63;
        xs[li][d] = xin[(size_t)(n0 + li) * FIN + d];
    }
    __syncthreads();
    int li = t >> 6, o = t & 63;
    float acc = b[o];
#pragma unroll
    for (int d = 0; d < FIN; d++) acc += xs[li][d] * ws[d * DD + o];
    d_x[(size_t)(n0 + li) * DD + o] = fmaxf(acc, 0.0f);
}

// ---------------- edge hidden, transposed: hT[k][e] = relu(ea @ W1 + b1) ----------
__global__ __launch_bounds__(256) void k_edge_h(const float* __restrict__ ea,
                                                const float* __restrict__ w1,
                                                const float* __restrict__ b1) {
    __shared__ float ws[EIN * HE];
    __shared__ float bs[HE];
    int t = threadIdx.x;
    for (int i = t; i < EIN * HE; i += 256) ws[i] = w1[i];
    if (t < HE) bs[t] = b1[t];
    __syncthreads();
    int e = blockIdx.x * 128 + (t & 127);
    int k0 = (t >> 7) * 32;
    float ev[EIN];
    const float4* ep = (const float4*)(ea + (size_t)e * EIN);
#pragma unroll
    for (int i = 0; i < 4; i++) {
        float4 v = ep[i];
        ev[4 * i + 0] = v.x; ev[4 * i + 1] = v.y;
        ev[4 * i + 2] = v.z; ev[4 * i + 3] = v.w;
    }
    float acc[32];
#pragma unroll
    for (int kk = 0; kk < 32; kk++) acc[kk] = bs[k0 + kk];
#pragma unroll
    for (int j = 0; j < EIN; j++) {
        float evj = ev[j];
#pragma unroll
        for (int kk = 0; kk < 32; kk++) acc[kk] += evj * ws[j * HE + k0 + kk];
    }
#pragma unroll
    for (int kk = 0; kk < 32; kk++)
        d_hT[(size_t)(k0 + kk) * EE + e] = fmaxf(acc[kk], 0.0f);
}

// ---------------- edge message GEMM via warp MMA (single-pass fp16) ---------------
// Block: 128 edges, 4 warps. Warp tile: 32 edges x 64 outputs.
// B/h staged via cp.async double-buffer. ONLY change vs R10: alo pass removed.
__global__ __launch_bounds__(128) void k_edge_msg_hmma(const int* __restrict__ src,
                                                       const int* __restrict__ dst,
                                                       int layer) {
    __shared__ __half Bs[2][BCH16];  // 2 x 9216 B
    __shared__ float hs[2][128];

    int t = threadIdx.x, wid = t >> 5, lid = t & 31;
    int g = lid >> 2, tig = lid & 3;
    int e0 = blockIdx.x * 128;

    // ---- y fragments in registers (constant across chunks) ----
    float yv[4][16];
    int edge_id[4];
#pragma unroll
    for (int mt = 0; mt < 2; mt++)
#pragma unroll
        for (int rr = 0; rr < 2; rr++) {
            int e = e0 + wid * 32 + mt * 16 + g + rr * 8;
            edge_id[mt * 2 + rr] = e;
            const float* xr = d_x + (size_t)src[e] * DD;
#pragma unroll
            for (int w = 0; w < 4; w++) {
                float2 v0 = *(const float2*)(xr + w * 16 + tig * 2);
                float2 v1 = *(const float2*)(xr + w * 16 + 8 + tig * 2);
                yv[mt * 2 + rr][w * 4 + 0] = v0.x;
                yv[mt * 2 + rr][w * 4 + 1] = v0.y;
                yv[mt * 2 + rr][w * 4 + 2] = v1.x;
                yv[mt * 2 + rr][w * 4 + 3] = v1.y;
            }
        }

    float acc[2][8][4];
#pragma unroll
    for (int mt = 0; mt < 2; mt++)
#pragma unroll
        for (int nt = 0; nt < 8; nt++)
#pragma unroll
            for (int q = 0; q < 4; q++) acc[mt][nt][q] = 0.0f;

    const __half* Bh = d_Bh + (size_t)layer * NCHUNK * BCH16;

    uint32_t sB0 = smem_u32(&Bs[0][0]);
    uint32_t sB1 = smem_u32(&Bs[1][0]);
    uint32_t sh0 = smem_u32(&hs[0][0]);
    uint32_t sh1 = smem_u32(&hs[1][0]);

    auto issue_chunk = [&](int kc, int st) {
        const char* gB = (const char*)(Bh + (size_t)kc * BCH16);
        uint32_t sB = st ? sB1 : sB0;
        uint32_t sh = st ? sh1 : sh0;
#pragma unroll
        for (int q = 0; q < 4; q++)
            CP_A16(sB + (t + q * 128) * 16, gB + (size_t)(t + q * 128) * 16);
        if (t < 64) CP_A16(sB + (t + 512) * 16, gB + (size_t)(t + 512) * 16);
        CP_A4(sh + t * 4, (const char*)(d_hT + (size_t)kc * EE + e0 + t));
    };

    issue_chunk(0, 0);
    CP_COMMIT();

    for (int kc = 0; kc < NCHUNK; kc++) {
        int st = kc & 1;
        __syncthreads();
        if (kc + 1 < NCHUNK) {
            issue_chunk(kc + 1, st ^ 1);
            CP_COMMIT();
            CP_WAIT1();
        } else {
            CP_WAIT0();
        }
        __syncthreads();

        float h0  = hs[st][wid * 32 + g];
        float h0b = hs[st][wid * 32 + g + 8];
        float h1  = hs[st][wid * 32 + 16 + g];
        float h1b = hs[st][wid * 32 + 16 + g + 8];

#pragma unroll
        for (int w = 0; w < 4; w++) {
            uint32_t ah[2][4];
#pragma unroll
            for (int mt = 0; mt < 2; mt++) {
                float ha = mt ? h1 : h0;
                float hb = mt ? h1b : h0b;
                const float* y0 = yv[mt * 2 + 0];  // row g
                const float* y1 = yv[mt * 2 + 1];  // row g+8
                ah[mt][0] = packh2(ha * y0[w * 4 + 0], ha * y0[w * 4 + 1]);
                ah[mt][1] = packh2(hb * y1[w * 4 + 0], hb * y1[w * 4 + 1]);
                ah[mt][2] = packh2(ha * y0[w * 4 + 2], ha * y0[w * 4 + 3]);
                ah[mt][3] = packh2(hb * y1[w * 4 + 2], hb * y1[w * 4 + 3]);
            }
#pragma unroll
            for (int nt = 0; nt < 8; nt++) {
                int boff = (nt * 8 + g) * BSTRIDE + w * 16 + tig * 2;
                uint32_t b0 = *(const uint32_t*)(&Bs[st][0] + boff);
                uint32_t b1 = *(const uint32_t*)(&Bs[st][0] + boff + 8);
#pragma unroll
                for (int mt = 0; mt < 2; mt++)
                    hmma(acc[mt][nt], ah[mt][0], ah[mt][1], ah[mt][2], ah[mt][3], b0, b1);
            }
        }
    }

    // ---- scatter: agg[dst] += msg / deg ----
#pragma unroll
    for (int mt = 0; mt < 2; mt++)
#pragma unroll
        for (int rr = 0; rr < 2; rr++) {
            int e = edge_id[mt * 2 + rr];
            int dn = dst[e];
            float ic = d_invc[dn];
            float* p = d_agg + (size_t)dn * DD + tig * 2;
#pragma unroll
            for (int nt = 0; nt < 8; nt++) {
                atomicAdd(&p[nt * 8 + 0], acc[mt][nt][rr * 2 + 0] * ic);
                atomicAdd(&p[nt * 8 + 1], acc[mt][nt][rr * 2 + 1] * ic);
            }
        }
}

// ---------------- root: xc = relu(agg + x @ root_w + b) ----------------
__global__ __launch_bounds__(256) void k_root(const float* __restrict__ w,
                                              const float* __restrict__ b) {
    __shared__ float ws[DD * DD];
    __shared__ float xs[4][DD];
    int t = threadIdx.x;
    for (int i = t; i < DD * DD; i += 256) ws[i] = w[i];
    int n0 = blockIdx.x * 4;
    {
        int li = t >> 6, d = t & 63;
        xs[li][d] = d_x[(size_t)(n0 + li) * DD + d];
    }
    __syncthreads();
    int li = t >> 6, o = t & 63;
    size_t idx = (size_t)(n0 + li) * DD + o;
    float acc = b[o] + d_agg[idx];
#pragma unroll
    for (int d = 0; d < DD; d++) acc += xs[li][d] * ws[d * DD + o];
    d_agg[idx] = fmaxf(acc, 0.0f);
}

// ---------------- GraphNorm + residual (one block per graph) ----------------
__global__ __launch_bounds__(256) void k_gnorm(const float* __restrict__ gw,
                                               const float* __restrict__ gb,
                                               const float* __restrict__ gs) {
    __shared__ float s[128][DD + 1];
    __shared__ float mean[DD];
    __shared__ float var[DD];
    int g = blockIdx.x, t = threadIdx.x;
    const float* xc = d_agg + (size_t)g * 128 * DD;
    for (int i = t; i < 128 * DD; i += 256) s[i >> 6][i & 63] = xc[i];
    __syncthreads();
    if (t < DD) {
        float m = 0.0f;
        for (int n = 0; n < 128; n++) m += s[n][t];
        mean[t] = m * (1.0f / 128.0f);
    }
    __syncthreads();
    for (int i = t; i < 128 * DD; i += 256) {
        int n = i >> 6, d = i & 63;
        s[n][d] -= gs[d] * mean[d];
    }
    __syncthreads();
    if (t < DD) {
        float v = 0.0f;
        for (int n = 0; n < 128; n++) v += s[n][t] * s[n][t];
        var[t] = v * (1.0f / 128.0f);
    }
    __syncthreads();
    for (int i = t; i < 128 * DD; i += 256) {
        int n = i >> 6, d = i & 63;
        float xn = gw[d] * s[n][d] * rsqrtf(var[d] + EPSV) + gb[d];
        size_t gi = (size_t)g * 128 * DD + i;
        d_x[gi] = xn + d_x[gi];
    }
}

// ---------------- Set2Set (3 steps) + head, one block per graph ----------------
__global__ __launch_bounds__(128) void k_s2s(const float* __restrict__ wih,
                                             const float* __restrict__ whh,
                                             const float* __restrict__ bih,
                                             const float* __restrict__ bhh,
                                             const float* __restrict__ hw1,
                                             const float* __restrict__ hb1,
                                             const float* __restrict__ hw2,
                                             const float* __restrict__ hb2,
                                             float* __restrict__ out) {
    __shared__ float sx[128][DD + 1];
    __shared__ float q_star[2 * DD];
    __shared__ float sh[DD], sc[DD];
    __shared__ float gates[4 * DD];
    __shared__ float red[128];
    __shared__ float sa[128];
    __shared__ float sr[DD];
    int g = blockIdx.x, t = threadIdx.x;
    const float* xg = d_x + (size_t)g * 128 * DD;
    for (int i = t; i < 128 * DD; i += 128) sx[i >> 6][i & 63] = xg[i];
    q_star[t] = 0.0f;
    if (t < DD) { sh[t] = 0.0f; sc[t] = 0.0f; }
    __syncthreads();

    for (int step = 0; step < NSTEPS; step++) {
#pragma unroll
        for (int rr = 0; rr < 2; rr++) {
            int r = t + rr * 128;
            float acc = bih[r] + bhh[r];
            const float* wr = wih + (size_t)r * (2 * DD);
            for (int j = 0; j < 2 * DD; j++) acc += q_star[j] * wr[j];
            const float* vr = whh + (size_t)r * DD;
            for (int j = 0; j < DD; j++) acc += sh[j] * vr[j];
            gates[r] = acc;
        }
        __syncthreads();
        if (t < DD) {
            float ig = 1.0f / (1.0f + expf(-gates[t]));
            float fg = 1.0f / (1.0f + expf(-gates[DD + t]));
            float gg = tanhf(gates[2 * DD + t]);
            float og = 1.0f / (1.0f + expf(-gates[3 * DD + t]));
            float c = fg * sc[t] + ig * gg;
            sc[t] = c;
            sh[t] = og * tanhf(c);
        }
        __syncthreads();
        float ee = 0.0f;
#pragma unroll
        for (int d = 0; d < DD; d++) ee += sx[t][d] * sh[d];
        red[t] = ee;
        __syncthreads();
        for (int off = 64; off; off >>= 1) {
            if (t < off) red[t] = fmaxf(red[t], red[t + off]);
            __syncthreads();
        }
        float emax = red[0];
        __syncthreads();
        float ex = expf(ee - emax);
        red[t] = ex;
        __syncthreads();
        for (int off = 64; off; off >>= 1) {
            if (t < off) red[t] += red[t + off];
            __syncthreads();
        }
        float denom = red[0];
        sa[t] = ex / denom;
        __syncthreads();
        if (t < DD) {
            float r = 0.0f;
            for (int n = 0; n < 128; n++) r += sa[n] * sx[n][t];
            sr[t] = r;
        }
        __syncthreads();
        q_star[t] = (t < DD) ? sh[t] : sr[t - DD];
        __syncthreads();
    }
    if (t < DD) {
        float acc = hb1[t];
        for (int j = 0; j < 2 * DD; j++) acc += q_star[j] * hw1[j * DD + t];
        red[t] = fmaxf(acc, 0.0f) * hw2[t];
    }
    __syncthreads();
    if (t < 32) {
        float v = red[t] + red[t + 32];
        for (int off = 16; off; off >>= 1) v += __shfl_down_sync(0xffffffffu, v, off);
        if (t == 0) out[g] = v + hb2[0];
    }
}

// ---------------- launch ----------------
extern "C" void kernel_launch(void* const* d_in, const int* in_sizes, int n_in,
                              void* d_out, int out_size) {
    const float* x     = (const float*)d_in[0];
    const int*   ei    = (const int*)d_in[1];
    const float* ea    = (const float*)d_in[2];
    const float* lin0w = (const float*)d_in[4];
    const float* lin0b = (const float*)d_in[5];
    const float* mw1   = (const float*)d_in[6];
    const float* mb1   = (const float*)d_in[7];
    const float* mw2   = (const float*)d_in[8];
    const float* mb2   = (const float*)d_in[9];
    const float* rootw = (const float*)d_in[10];
    const float* convb = (const float*)d_in[11];
    const float* gnw   = (const float*)d_in[12];
    const float* gnb   = (const float*)d_in[13];
    const float* gns   = (const float*)d_in[14];
    const float* wih   = (const float*)d_in[15];
    const float* whh   = (const float*)d_in[16];
    const float* bih   = (const float*)d_in[17];
    const float* bhh   = (const float*)d_in[18];
    const float* hw1   = (const float*)d_in[19];
    const float* hb1   = (const float*)d_in[20];
    const float* hw2   = (const float*)d_in[21];
    const float* hb2   = (const float*)d_in[22];
    float* out = (float*)d_out;

    const int* src = ei;
    const int* dst = ei + EE;

    k_zero_cnt<<<NN / 256, 256>>>();
    k_count<<<EE / 256, 256>>>(dst);
    k_invc<<<NN / 256, 256>>>();
    k_lin0<<<NN / 4, 256>>>(x, lin0w, lin0b);
    k_prep_B<<<LL * NCHUNK, 256>>>(mw2, mb2);
    k_ones<<<EE / 256, 256>>>();

    for (int l = 0; l < LL; l++) {
        k_zero_agg<<<(NN * DD) / 256, 256>>>();
        k_edge_h<<<EE / 128, 256>>>(ea, mw1 + (size_t)l * EIN * HE, mb1 + (size_t)l * HE);
        k_edge_msg_hmma<<<EE / 128, 128>>>(src, dst, l);
        k_root<<<NN / 4, 256>>>(rootw + (size_t)l * DD * DD, convb + (size_t)l * DD);
        k_gnorm<<<GG, 256>>>(gnw + (size_t)l * DD, gnb + (size_t)l * DD, gns + (size_t)l * DD);
    }

    k_s2s<<<GG, 128>>>(wih, whh, bih, bhh, hw1, hb1, hw2, hb2, out);
}